// round 8
// baseline (speedup 1.0000x reference)
#include <cuda_runtime.h>
#include <math.h>

#define BATCH     32768
#define IN_DIM    64
#define NUM_BINS  10
#define EMBED_DIM 64
#define NTHRESH   9

#define GRID   444                // 148 SMs * 3 blocks co-resident (<=83 regs)
#define TPB    256
#define MMB    (GRID - 1)         // blocks 0..442 min/max; block 443 bins+M
#define T1     (MMB * TPB)        // %16==0 -> float4 column-group invariant
#define NV     (BATCH * 16)
#define NWARP  (GRID * 8)         // 3552 phase-2 warps

#define E8(x)  x,x,x,x,x,x,x,x
#define E64(x) E8(x),E8(x),E8(x),E8(x),E8(x),E8(x),E8(x),E8(x)

// monotone float<->uint encoding: unsigned order == float order (NaN-free data)
__device__ __forceinline__ unsigned fenc(float f) {
    unsigned u = __float_as_uint(f);
    return (u & 0x80000000u) ? ~u : (u | 0x80000000u);
}
__device__ __forceinline__ float fdec(unsigned e) {
    unsigned u = (e & 0x80000000u) ? (e ^ 0x80000000u) : ~e;
    return __uint_as_float(u);
}

// ---- scratch (device globals; no allocation allowed) ----
__device__ unsigned g_minenc[IN_DIM] = { E64(0xFF800000u) };  // enc(+INF)
__device__ unsigned g_maxenc[IN_DIM] = { E64(0x007FFFFFu) };  // enc(-INF)
__device__ float    g_bins[NTHRESH];
__device__ float    g_thr[IN_DIM * NTHRESH];   // thr[c][k]: pred <=> x > thr
__device__ float    g_M[NUM_BINS * EMBED_DIM];
__device__ int      g_count;
__device__ unsigned g_release;

// exact boundary: largest float X with fdiv_rn(fsub_rn(X,mn),dn) <= bk
// (predicate is weakly monotone in x; search in monotone-uint space)
__device__ float find_thr(float mn, float dn, float bk) {
    const unsigned ELO = 0x007FFFFFu;   // enc(-inf): predicate false
    const unsigned EHI = 0xFF800000u;   // enc(+inf): predicate true
    double gd = (double)mn + (double)bk * (double)dn;
    float gf = (float)gd;
    if (!isfinite(gf)) gf = (gd > 0.0) ? 3.0e38f : -3.0e38f;
    unsigned ge = fenc(gf);
    if (ge < ELO) ge = ELO;
    if (ge > EHI) ge = EHI;

    unsigned lo, hi;
    if (__fdiv_rn(fdec(ge) - mn, dn) > bk) {
        hi = ge; lo = ELO;
        unsigned step = 1;
        unsigned p = ge;
        while (p > ELO) {
            p = (p - ELO > step) ? p - step : ELO;
            if (!(__fdiv_rn(fdec(p) - mn, dn) > bk)) { lo = p; break; }
            hi = p;
            step <<= 1;
        }
    } else {
        lo = ge; hi = EHI;
        unsigned step = 1;
        unsigned p = ge;
        while (p < EHI) {
            p = (EHI - p > step) ? p + step : EHI;
            if (__fdiv_rn(fdec(p) - mn, dn) > bk) { hi = p; break; }
            lo = p;
            step <<= 1;
        }
    }
    while (hi - lo > 1) {
        unsigned mid = lo + ((hi - lo) >> 1);
        if (__fdiv_rn(fdec(mid) - mn, dn) > bk) hi = mid; else lo = mid;
    }
    return fdec(lo);
}

__global__ void __launch_bounds__(TPB, 3)
dybem_fused(const float*  __restrict__ x,
            const float*  __restrict__ logits,
            const float*  __restrict__ embed,
            const float*  __restrict__ W,
            const float*  __restrict__ bias,
            float*        __restrict__ out) {
    const int tid  = threadIdx.x;
    const int lane = tid & 31;
    const int wrp  = tid >> 5;
    const int b    = blockIdx.x;

    __shared__ unsigned s_snap;
    __shared__ int      s_ticket;
    __shared__ float smm[2][8][16][4];
    __shared__ float sWt[EMBED_DIM * 65];
    __shared__ float sEm[NUM_BINS * EMBED_DIM];
    __shared__ float sE[NUM_BINS];
    __shared__ float sMn[IN_DIM], sDn[IN_DIM];   // finalize-block scratch

    if (tid == 0) s_snap = *(volatile unsigned*)&g_release;
    __syncthreads();

    // ================= PHASE 1 =================
    if (b < MMB) {
        const float4* __restrict__ x4 = (const float4*)x;
        const int tg = b * TPB + tid;
        float mn0 =  INFINITY, mn1 =  INFINITY, mn2 =  INFINITY, mn3 =  INFINITY;
        float mx0 = -INFINITY, mx1 = -INFINITY, mx2 = -INFINITY, mx3 = -INFINITY;
        #pragma unroll 5
        for (int idx = tg; idx < NV; idx += T1) {
            float4 v = x4[idx];
            mn0 = fminf(mn0, v.x); mx0 = fmaxf(mx0, v.x);
            mn1 = fminf(mn1, v.y); mx1 = fmaxf(mx1, v.y);
            mn2 = fminf(mn2, v.z); mx2 = fmaxf(mx2, v.z);
            mn3 = fminf(mn3, v.w); mx3 = fmaxf(mx3, v.w);
        }
        mn0 = fminf(mn0, __shfl_down_sync(0xffffffffu, mn0, 16));
        mn1 = fminf(mn1, __shfl_down_sync(0xffffffffu, mn1, 16));
        mn2 = fminf(mn2, __shfl_down_sync(0xffffffffu, mn2, 16));
        mn3 = fminf(mn3, __shfl_down_sync(0xffffffffu, mn3, 16));
        mx0 = fmaxf(mx0, __shfl_down_sync(0xffffffffu, mx0, 16));
        mx1 = fmaxf(mx1, __shfl_down_sync(0xffffffffu, mx1, 16));
        mx2 = fmaxf(mx2, __shfl_down_sync(0xffffffffu, mx2, 16));
        mx3 = fmaxf(mx3, __shfl_down_sync(0xffffffffu, mx3, 16));
        if (lane < 16) {
            smm[0][wrp][lane][0] = mn0; smm[0][wrp][lane][1] = mn1;
            smm[0][wrp][lane][2] = mn2; smm[0][wrp][lane][3] = mn3;
            smm[1][wrp][lane][0] = mx0; smm[1][wrp][lane][1] = mx1;
            smm[1][wrp][lane][2] = mx2; smm[1][wrp][lane][3] = mx3;
        }
        __syncthreads();
        if (tid < IN_DIM) {
            const int g = tid >> 2, q = tid & 3;
            float a =  INFINITY, c = -INFINITY;
            #pragma unroll
            for (int w = 0; w < 8; w++) {
                a = fminf(a, smm[0][w][g][q]);
                c = fmaxf(c, smm[1][w][g][q]);
            }
            atomicMin(&g_minenc[tid], fenc(a));
            atomicMax(&g_maxenc[tid], fenc(c));
        }
    } else {
        // --- block MMB: bins (warp 0, parallel exp) + M = embed @ W^T ---
        if (wrp == 0) {
            float li = (lane < NUM_BINS) ? logits[lane] : -INFINITY;
            float m = li;
            #pragma unroll
            for (int d = 16; d >= 1; d >>= 1)
                m = fmaxf(m, __shfl_xor_sync(0xffffffffu, m, d));
            if (lane < NUM_BINS)
                sE[lane] = (float)exp((double)(li - m));  // 10 parallel exp chains
            __syncwarp();
            if (lane == 0) {
                float s = 0.f;
                #pragma unroll
                for (int i = 0; i < NUM_BINS; i++) s += sE[i];   // same serial order
                float cum = 0.f;
                #pragma unroll
                for (int i = 0; i < NUM_BINS; i++) {
                    cum += __fdiv_rn(sE[i], s);                   // IEEE div
                    if (i < NTHRESH) g_bins[i] = cum;
                }
            }
        }
        #pragma unroll
        for (int i = tid; i < EMBED_DIM * EMBED_DIM; i += TPB) {
            const int f = i >> 6, e = i & 63;
            sWt[e * 65 + f] = W[i];           // coalesced read, conflict-free write
        }
        for (int i = tid; i < NUM_BINS * EMBED_DIM; i += TPB)
            sEm[i] = embed[i];
        __syncthreads();
        for (int i = tid; i < NUM_BINS * EMBED_DIM; i += TPB) {
            const int k = i >> 6, f = i & 63;
            const float* em = sEm + k * EMBED_DIM;
            float s = 0.f;
            #pragma unroll 16
            for (int e2 = 0; e2 < EMBED_DIM; e2++)
                s = fmaf(em[e2], sWt[e2 * 65 + f], s);
            g_M[i] = s;
        }
    }

    // ================= GRID BARRIER =================
    __threadfence();
    __syncthreads();
    if (tid == 0) s_ticket = atomicAdd(&g_count, 1);
    __syncthreads();

    if (s_ticket == GRID - 1) {
        __threadfence();  // acquire all atomics + g_bins
        if (tid < IN_DIM) {
            float a = fdec(*(volatile unsigned*)&g_minenc[tid]);
            float c = fdec(*(volatile unsigned*)&g_maxenc[tid]);
            sMn[tid] = a;
            sDn[tid] = (c - a) + 1e-6f;
            g_minenc[tid] = 0xFF800000u;   // reset for next graph replay
            g_maxenc[tid] = 0x007FFFFFu;
        }
        __syncthreads();
        // exact per-(col,k) thresholds: 576 searches over 256 threads
        for (int i = tid; i < IN_DIM * NTHRESH; i += TPB) {
            const int c = i / NTHRESH, k = i % NTHRESH;
            g_thr[i] = find_thr(sMn[c], sDn[c], g_bins[k]);
        }
        if (tid == 0) g_count = 0;
        __threadfence();
        __syncthreads();
        if (tid == 0) atomicAdd(&g_release, 1u);
    }

    if (tid == 0) {
        while (*(volatile unsigned*)&g_release == s_snap) { __nanosleep(32); }
    }
    __syncthreads();
    __threadfence();

    // ================= PHASE 2 =================
    // out[b,f] = 64*(M[0][f]+bias[f]) + sum_{k=1..9} c_k * (M[k][f]-M[k-1][f])
    // predicate (xn > bins[k]) == (x > thr[c][k]) exactly. No div/sub in loop.
    const int c0 = lane * 2;
    const int c1 = c0 + 1;
    const int w  = b * 8 + wrp;

    float t0[NTHRESH], t1[NTHRESH];
    #pragma unroll
    for (int k = 0; k < NTHRESH; k++) {
        t0[k] = g_thr[c0 * NTHRESH + k];
        t1[k] = g_thr[c1 * NTHRESH + k];
    }

    const float base0 = 64.f * (g_M[c0] + bias[c0]);
    const float base1 = 64.f * (g_M[c1] + bias[c1]);

    float D0[NTHRESH], D1[NTHRESH];
    #pragma unroll
    for (int k = 0; k < NTHRESH; k++) {
        D0[k] = g_M[(k + 1) * EMBED_DIM + c0] - g_M[k * EMBED_DIM + c0];
        D1[k] = g_M[(k + 1) * EMBED_DIM + c1] - g_M[k * EMBED_DIM + c1];
    }

    const float2* __restrict__ x2   = (const float2*)x;
    float2* __restrict__       out2 = (float2*)out;

    int r           = (int)(((long long)w       * BATCH) / NWARP);
    const int r_end = (int)(((long long)(w + 1) * BATCH) / NWARP);

    for (; r + 4 <= r_end; r += 4) {
        const float2* xp = x2 + r * 32 + lane;
        float2 v0 = xp[0];
        float2 v1 = xp[32];
        float2 v2 = xp[64];
        float2 v3 = xp[96];

        unsigned qa0 = 0, qa1 = 0, qa2 = 0;
        unsigned qb0 = 0, qb1 = 0, qb2 = 0;
        unsigned qc0 = 0, qc1 = 0, qc2 = 0;
        unsigned qd0 = 0, qd1 = 0, qd2 = 0;
        #pragma unroll
        for (int k = 0; k < 4; k++) {
            const unsigned wgt = 1u << (8 * k);
            qa0 += (v0.x > t0[k]) ? wgt : 0u;  qa0 += (v0.y > t1[k]) ? wgt : 0u;
            qb0 += (v1.x > t0[k]) ? wgt : 0u;  qb0 += (v1.y > t1[k]) ? wgt : 0u;
            qc0 += (v2.x > t0[k]) ? wgt : 0u;  qc0 += (v2.y > t1[k]) ? wgt : 0u;
            qd0 += (v3.x > t0[k]) ? wgt : 0u;  qd0 += (v3.y > t1[k]) ? wgt : 0u;
        }
        #pragma unroll
        for (int k = 4; k < 8; k++) {
            const unsigned wgt = 1u << (8 * (k - 4));
            qa1 += (v0.x > t0[k]) ? wgt : 0u;  qa1 += (v0.y > t1[k]) ? wgt : 0u;
            qb1 += (v1.x > t0[k]) ? wgt : 0u;  qb1 += (v1.y > t1[k]) ? wgt : 0u;
            qc1 += (v2.x > t0[k]) ? wgt : 0u;  qc1 += (v2.y > t1[k]) ? wgt : 0u;
            qd1 += (v3.x > t0[k]) ? wgt : 0u;  qd1 += (v3.y > t1[k]) ? wgt : 0u;
        }
        qa2 += (v0.x > t0[8]) ? 1u : 0u;  qa2 += (v0.y > t1[8]) ? 1u : 0u;
        qb2 += (v1.x > t0[8]) ? 1u : 0u;  qb2 += (v1.y > t1[8]) ? 1u : 0u;
        qc2 += (v2.x > t0[8]) ? 1u : 0u;  qc2 += (v2.y > t1[8]) ? 1u : 0u;
        qd2 += (v3.x > t0[8]) ? 1u : 0u;  qd2 += (v3.y > t1[8]) ? 1u : 0u;

        qa0 = __reduce_add_sync(0xffffffffu, qa0);
        qa1 = __reduce_add_sync(0xffffffffu, qa1);
        qa2 = __reduce_add_sync(0xffffffffu, qa2);
        qb0 = __reduce_add_sync(0xffffffffu, qb0);
        qb1 = __reduce_add_sync(0xffffffffu, qb1);
        qb2 = __reduce_add_sync(0xffffffffu, qb2);
        qc0 = __reduce_add_sync(0xffffffffu, qc0);
        qc1 = __reduce_add_sync(0xffffffffu, qc1);
        qc2 = __reduce_add_sync(0xffffffffu, qc2);
        qd0 = __reduce_add_sync(0xffffffffu, qd0);
        qd1 = __reduce_add_sync(0xffffffffu, qd1);
        qd2 = __reduce_add_sync(0xffffffffu, qd2);

        float a0 = base0, a1 = base1, b0 = base0, b1 = base1;
        float cc0 = base0, cc1 = base1, d0 = base0, d1 = base1;
        #pragma unroll
        for (int k = 0; k < 9; k++) {
            unsigned ca = (k < 4) ? (qa0 >> (8 * k)) : ((k < 8) ? (qa1 >> (8 * (k - 4))) : qa2);
            unsigned cb = (k < 4) ? (qb0 >> (8 * k)) : ((k < 8) ? (qb1 >> (8 * (k - 4))) : qb2);
            unsigned cg = (k < 4) ? (qc0 >> (8 * k)) : ((k < 8) ? (qc1 >> (8 * (k - 4))) : qc2);
            unsigned cd = (k < 4) ? (qd0 >> (8 * k)) : ((k < 8) ? (qd1 >> (8 * (k - 4))) : qd2);
            float fa = (float)(ca & 0xffu);
            float fb = (float)(cb & 0xffu);
            float fc = (float)(cg & 0xffu);
            float fd = (float)(cd & 0xffu);
            a0  = fmaf(fa, D0[k], a0);   a1  = fmaf(fa, D1[k], a1);
            b0  = fmaf(fb, D0[k], b0);   b1  = fmaf(fb, D1[k], b1);
            cc0 = fmaf(fc, D0[k], cc0);  cc1 = fmaf(fc, D1[k], cc1);
            d0  = fmaf(fd, D0[k], d0);   d1  = fmaf(fd, D1[k], d1);
        }
        float2* op = out2 + r * 32 + lane;
        op[0]  = make_float2(a0, a1);
        op[32] = make_float2(b0, b1);
        op[64] = make_float2(cc0, cc1);
        op[96] = make_float2(d0, d1);
    }

    for (; r < r_end; r++) {
        float2 v0 = x2[r * 32 + lane];
        unsigned qa0 = 0, qa1 = 0, qa2 = 0;
        #pragma unroll
        for (int k = 0; k < 4; k++) {
            const unsigned wgt = 1u << (8 * k);
            qa0 += (v0.x > t0[k]) ? wgt : 0u;  qa0 += (v0.y > t1[k]) ? wgt : 0u;
        }
        #pragma unroll
        for (int k = 4; k < 8; k++) {
            const unsigned wgt = 1u << (8 * (k - 4));
            qa1 += (v0.x > t0[k]) ? wgt : 0u;  qa1 += (v0.y > t1[k]) ? wgt : 0u;
        }
        qa2 += (v0.x > t0[8]) ? 1u : 0u;  qa2 += (v0.y > t1[8]) ? 1u : 0u;

        qa0 = __reduce_add_sync(0xffffffffu, qa0);
        qa1 = __reduce_add_sync(0xffffffffu, qa1);
        qa2 = __reduce_add_sync(0xffffffffu, qa2);

        float a0 = base0, a1 = base1;
        #pragma unroll
        for (int k = 0; k < 9; k++) {
            unsigned ca = (k < 4) ? (qa0 >> (8 * k)) : ((k < 8) ? (qa1 >> (8 * (k - 4))) : qa2);
            float fa = (float)(ca & 0xffu);
            a0 = fmaf(fa, D0[k], a0);
            a1 = fmaf(fa, D1[k], a1);
        }
        out2[r * 32 + lane] = make_float2(a0, a1);
    }
}

extern "C" void kernel_launch(void* const* d_in, const int* in_sizes, int n_in,
                              void* d_out, int out_size) {
    const float* x      = (const float*)d_in[0];
    const float* logits = (const float*)d_in[1];
    const float* embed  = (const float*)d_in[2];
    const float* W      = (const float*)d_in[3];
    const float* bias   = (const float*)d_in[4];
    float* out          = (float*)d_out;

    dybem_fused<<<GRID, TPB>>>(x, logits, embed, W, bias, out);
}